// round 4
// baseline (speedup 1.0000x reference)
#include <cuda_runtime.h>
#include <cstdint>

// Shapes (fixed by the problem)
#define NB 2
#define NN 1024
#define NE 256
#define NH 64
#define ND 64
#define NHM 128

// Output layout: samples[2*2^20], mask_scores[2*2^20], entropy[2*2^20], w[1024]
#define HALF (1u << 20)           // N*N = 1048576
#define OUT_TOTAL_PER (2097152)   // 2 * 2^20

// Scratch: P = exp(2 * enc@wl), Q = exp(2 * enc@wr)
__device__ float g_P[NB * NN * NH];
__device__ float g_Q[NB * NN * NH];

__device__ __forceinline__ float frcp(float x) {
    float y;
    asm("rcp.approx.f32 %0, %1;" : "=f"(y) : "f"(x));
    return y;
}

// ---------------------------------------------------------------------------
// Threefry-2x32, 20 rounds, key = (0, 1)  (jax.random.key(1)).
// Partitionable scheme (modern JAX default): element with flat index m uses
// counter (hi32(m), lo32(m)) = (0, m).  For bit_width in [8,16,32], JAX's
// _threefry_random_bits_partitionable returns  bits1 ^ bits2  — the XOR of
// the two cipher output words.
// ---------------------------------------------------------------------------
__device__ __forceinline__ uint32_t threefry_bits32(uint32_t x0, uint32_t x1) {
    const uint32_t ks0 = 0u;
    const uint32_t ks1 = 1u;
    const uint32_t ks2 = 0x1BD11BDAu ^ ks0 ^ ks1;  // 0x1BD11BDB

#define TF_ROUND(r) { x0 += x1; x1 = __funnelshift_l(x1, x1, (r)); x1 ^= x0; }

    x0 += ks0; x1 += ks1;
    TF_ROUND(13) TF_ROUND(15) TF_ROUND(26) TF_ROUND(6)
    x0 += ks1; x1 += ks2 + 1u;
    TF_ROUND(17) TF_ROUND(29) TF_ROUND(16) TF_ROUND(24)
    x0 += ks2; x1 += ks0 + 2u;
    TF_ROUND(13) TF_ROUND(15) TF_ROUND(26) TF_ROUND(6)
    x0 += ks0; x1 += ks1 + 3u;
    TF_ROUND(17) TF_ROUND(29) TF_ROUND(16) TF_ROUND(24)
    x0 += ks1; x1 += ks2 + 4u;
    TF_ROUND(13) TF_ROUND(15) TF_ROUND(26) TF_ROUND(6)
    x0 += ks2; x1 += ks0 + 5u;
#undef TF_ROUND
    return x0 ^ x1;   // bits1 ^ bits2 (JAX partitionable, bit_width=32)
}

__device__ __forceinline__ float bits_to_uniform(uint32_t b) {
    return __uint_as_float((b >> 9) | 0x3f800000u) - 1.0f;
}

// sigmoid / softplus epilogue (high precision: accurate expf + IEEE div)
__device__ __forceinline__ void finish(float s, float u01,
                                       float& samp, float& ent) {
    float e  = expf(-fabsf(s));
    float pm = 1.0f / (1.0f + e);
    float p  = (s >= 0.0f) ? pm : 1.0f - pm;
    float sp = fmaxf(s, 0.0f) + log1pf(e);
    ent  = sp - s * p;
    samp = (u01 < p) ? 1.0f : 0.0f;
}

// ---------------------------------------------------------------------------
// Kernel A: edge-weight MLP   w = softplus(relu(eq@W1+b1)@W2 + b2) + 1e-8
// one block per edge row, 128 threads (one per hidden unit)
// ---------------------------------------------------------------------------
__global__ void edge_mlp_kernel(const float* __restrict__ eq,
                                const float* __restrict__ w1,
                                const float* __restrict__ b1,
                                const float* __restrict__ w2,
                                const float* __restrict__ b2,
                                float* __restrict__ out_w) {
    __shared__ float row[ND];
    __shared__ float red[NHM];
    int r = blockIdx.x;
    int t = threadIdx.x;  // 128
    if (t < ND) row[t] = eq[r * ND + t];
    __syncthreads();
    float acc = b1[t];
#pragma unroll
    for (int d = 0; d < ND; ++d)
        acc = fmaf(row[d], w1[d * NHM + t], acc);
    acc = fmaxf(acc, 0.0f);
    red[t] = acc * w2[t];
    __syncthreads();
    for (int s = 64; s > 0; s >>= 1) {
        if (t < s) red[t] += red[t + s];
        __syncthreads();
    }
    if (t == 0) {
        float wlog = red[0] + b2[0];
        float e  = expf(-fabsf(wlog));
        float sp = fmaxf(wlog, 0.0f) + log1pf(e);
        out_w[r] = sp + 1e-8f;
    }
}

// ---------------------------------------------------------------------------
// Kernel B: P = exp(2*(enc@wl)), Q = exp(2*(enc@wr))
// [2048,256] @ [256,64] x 2.  Block handles 32 rows, 256 threads.
// thread col c in [0,128): c<64 -> wl output, c>=64 -> wr output.
// ---------------------------------------------------------------------------
#define BM 32
__global__ void proj_kernel(const float* __restrict__ enc,
                            const float* __restrict__ wl,
                            const float* __restrict__ wr) {
    __shared__ float Ws[64][128];   // k-chunk x (wl cols | wr cols)
    __shared__ float Es[BM][64];
    int t = threadIdx.x;            // 256
    int c = t & 127;
    int half = t >> 7;              // 0 or 1 -> which 16-row group
    int row0 = blockIdx.x * BM;

    float acc[16];
#pragma unroll
    for (int i = 0; i < 16; ++i) acc[i] = 0.0f;

    for (int k0 = 0; k0 < NE; k0 += 64) {
        __syncthreads();
#pragma unroll
        for (int i = 0; i < 32; ++i) {       // 64*128 / 256
            int idx = t + i * 256;
            int kk = idx >> 7, cc = idx & 127;
            float v = (cc < 64) ? wl[(k0 + kk) * 64 + cc]
                                : wr[(k0 + kk) * 64 + (cc - 64)];
            Ws[kk][cc] = v;
        }
#pragma unroll
        for (int i = 0; i < 8; ++i) {        // 32*64 / 256
            int idx = t + i * 256;
            int rr = idx >> 6, kk = idx & 63;
            Es[rr][kk] = enc[(row0 + rr) * NE + k0 + kk];
        }
        __syncthreads();
#pragma unroll 8
        for (int k = 0; k < 64; ++k) {
            float wv = Ws[k][c];
#pragma unroll
            for (int rr = 0; rr < 16; ++rr)
                acc[rr] = fmaf(Es[half * 16 + rr][k], wv, acc[rr]);
        }
    }
#pragma unroll
    for (int rr = 0; rr < 16; ++rr) {
        int row = row0 + half * 16 + rr;
        float v = expf(2.0f * acc[rr]);
        if (c < 64) g_P[row * 64 + c]        = v;
        else        g_Q[row * 64 + (c - 64)] = v;
    }
}

// ---------------------------------------------------------------------------
// Kernel C: main pair kernel.
// logits[b,i,j] = Usum + sum_h v_h / (P[b,i,h]*Q[b,j,h] + 1) + l_bias,
// with v_h = -2*u_h, Usum = sum_h u_h.
// Tile: 16 i x 64 j x both batches per block, 256 threads, 8 outputs each
// (2 i's x 2 j's x 2 batches).
// ---------------------------------------------------------------------------
#define TI 16
#define TJ 64
__global__ void __launch_bounds__(256) pair_kernel(
        const float* __restrict__ u,
        const float* __restrict__ l_bias,
        float* __restrict__ out) {
    __shared__ float ps[2 * TI * 64];        // [b][ii][h]
    __shared__ float qs[2 * TJ * 65];        // [b][jj][h], padded stride 65
    __shared__ float vs[64];

    int tid = threadIdx.x;                   // 256
    int i0 = blockIdx.y * TI;
    int j0 = blockIdx.x * TJ;

    if (tid < 64) vs[tid] = -2.0f * u[tid];
#pragma unroll
    for (int it = 0; it < (2 * TI * 64) / 256; ++it) {   // 8
        int idx = tid + it * 256;
        int b = idx >> 10;
        int rem = idx & 1023;
        int ii = rem >> 6, h = rem & 63;
        ps[idx] = g_P[(b * NN + i0 + ii) * 64 + h];
    }
#pragma unroll
    for (int it = 0; it < (2 * TJ * 64) / 256; ++it) {   // 32
        int idx = tid + it * 256;
        int b = idx >> 12;
        int rem = idx & 4095;
        int jj = rem >> 6, h = rem & 63;
        qs[(b * TJ + jj) * 65 + h] = g_Q[(b * NN + j0 + jj) * 64 + h];
    }
    __syncthreads();

    float Usum = 0.0f;
#pragma unroll
    for (int h = 0; h < 64; ++h) Usum += vs[h];
    Usum *= -0.5f;
    float sbase = Usum + l_bias[0];

    int w = tid >> 5, l = tid & 31;
    int ii0 = w * 2, ii1 = w * 2 + 1;

    const float* pA0 = ps + ii0 * 64;              // b0
    const float* pA1 = ps + ii1 * 64;
    const float* pB0 = ps + (TI + ii0) * 64;       // b1
    const float* pB1 = ps + (TI + ii1) * 64;
    const float* qA0 = qs + l * 65;                // b0, jj0 = l
    const float* qA1 = qs + (l + 32) * 65;         // b0, jj1 = l+32
    const float* qB0 = qs + (TJ + l) * 65;         // b1
    const float* qB1 = qs + (TJ + l + 32) * 65;

    float a000 = 0.f, a001 = 0.f, a010 = 0.f, a011 = 0.f;  // [b0][r][q]
    float a100 = 0.f, a101 = 0.f, a110 = 0.f, a111 = 0.f;  // [b1][r][q]

#pragma unroll 8
    for (int h = 0; h < 64; ++h) {
        float vh = vs[h];
        float p00 = pA0[h], p01 = pA1[h], p10 = pB0[h], p11 = pB1[h];
        float q00 = qA0[h], q01 = qA1[h], q10 = qB0[h], q11 = qB1[h];
        a000 = fmaf(vh, frcp(fmaf(p00, q00, 1.0f)), a000);
        a001 = fmaf(vh, frcp(fmaf(p00, q01, 1.0f)), a001);
        a010 = fmaf(vh, frcp(fmaf(p01, q00, 1.0f)), a010);
        a011 = fmaf(vh, frcp(fmaf(p01, q01, 1.0f)), a011);
        a100 = fmaf(vh, frcp(fmaf(p10, q10, 1.0f)), a100);
        a101 = fmaf(vh, frcp(fmaf(p10, q11, 1.0f)), a101);
        a110 = fmaf(vh, frcp(fmaf(p11, q10, 1.0f)), a110);
        a111 = fmaf(vh, frcp(fmaf(p11, q11, 1.0f)), a111);
    }

    float* out_s = out;
    float* out_m = out + OUT_TOTAL_PER;
    float* out_e = out + 2 * OUT_TOTAL_PER;

    float accs[2][2][2];
    accs[0][0][0] = a000; accs[0][0][1] = a001;
    accs[0][1][0] = a010; accs[0][1][1] = a011;
    accs[1][0][0] = a100; accs[1][0][1] = a101;
    accs[1][1][0] = a110; accs[1][1][1] = a111;

#pragma unroll
    for (int r = 0; r < 2; ++r) {
        int gi = i0 + ii0 + r;
#pragma unroll
        for (int q = 0; q < 2; ++q) {
            int gj = j0 + l + 32 * q;
            uint32_t n = (uint32_t)(gi * 1024 + gj);
            // Partitionable threefry: counter (0, flat_idx); bits = out0 ^ out1.
            float u0 = bits_to_uniform(threefry_bits32(0u, n));
            float u1 = bits_to_uniform(threefry_bits32(0u, n + HALF));
            float diag = (gi == gj) ? 1e8f : 0.0f;
            int m = gi * 1024 + gj;
            {
                float s = (sbase + accs[0][r][q]) - diag;
                float samp, ent;
                finish(s, u0, samp, ent);
                out_s[m] = samp; out_m[m] = s; out_e[m] = ent;
            }
            {
                float s = (sbase + accs[1][r][q]) - diag;
                float samp, ent;
                finish(s, u1, samp, ent);
                out_s[HALF + m] = samp; out_m[HALF + m] = s; out_e[HALF + m] = ent;
            }
        }
    }
}

// ---------------------------------------------------------------------------
extern "C" void kernel_launch(void* const* d_in, const int* in_sizes, int n_in,
                              void* d_out, int out_size) {
    (void)in_sizes; (void)n_in; (void)out_size;
    const float* enc = (const float*)d_in[0];
    const float* wl  = (const float*)d_in[1];
    const float* wr  = (const float*)d_in[2];
    const float* u   = (const float*)d_in[3];
    const float* lb  = (const float*)d_in[4];
    const float* eq  = (const float*)d_in[5];
    const float* w1  = (const float*)d_in[6];
    const float* b1  = (const float*)d_in[7];
    const float* w2  = (const float*)d_in[8];
    const float* b2  = (const float*)d_in[9];
    float* out = (float*)d_out;

    edge_mlp_kernel<<<NN, NHM>>>(eq, w1, b1, w2, b2, out + 3 * OUT_TOTAL_PER);
    proj_kernel<<<(NB * NN) / BM, 256>>>(enc, wl, wr);
    dim3 grid(NN / TJ, NN / TI);   // (16, 64)
    pair_kernel<<<grid, 256>>>(u, lb, out);
}

// round 5
// speedup vs baseline: 1.1002x; 1.1002x over previous
#include <cuda_runtime.h>
#include <cstdint>

#define NB 2
#define NN 1024
#define NE 256
#define NH 64
#define ND 64
#define NHM 128

#define HALF (1u << 20)           // N*N
#define OUT_TOTAL_PER (2097152)   // 2 * 2^20

__device__ float g_P[NB * NN * NH];
__device__ float g_Q[NB * NN * NH];

__device__ __forceinline__ float frcp(float x) {
    float y;
    asm("rcp.approx.f32 %0, %1;" : "=f"(y) : "f"(x));
    return y;
}

// Threefry-2x32, key=(0,1), partitionable: counter (0, m), bits = out0^out1.
__device__ __forceinline__ uint32_t threefry_bits32(uint32_t x0, uint32_t x1) {
    const uint32_t ks0 = 0u, ks1 = 1u;
    const uint32_t ks2 = 0x1BD11BDAu ^ ks0 ^ ks1;
#define TF_ROUND(r) { x0 += x1; x1 = __funnelshift_l(x1, x1, (r)); x1 ^= x0; }
    x0 += ks0; x1 += ks1;
    TF_ROUND(13) TF_ROUND(15) TF_ROUND(26) TF_ROUND(6)
    x0 += ks1; x1 += ks2 + 1u;
    TF_ROUND(17) TF_ROUND(29) TF_ROUND(16) TF_ROUND(24)
    x0 += ks2; x1 += ks0 + 2u;
    TF_ROUND(13) TF_ROUND(15) TF_ROUND(26) TF_ROUND(6)
    x0 += ks0; x1 += ks1 + 3u;
    TF_ROUND(17) TF_ROUND(29) TF_ROUND(16) TF_ROUND(24)
    x0 += ks1; x1 += ks2 + 4u;
    TF_ROUND(13) TF_ROUND(15) TF_ROUND(26) TF_ROUND(6)
    x0 += ks2; x1 += ks0 + 5u;
#undef TF_ROUND
    return x0 ^ x1;
}

__device__ __forceinline__ float bits_to_uniform(uint32_t b) {
    return __uint_as_float((b >> 9) | 0x3f800000u) - 1.0f;
}

__device__ __forceinline__ void finish(float s, float u01,
                                       float& samp, float& ent) {
    float e  = expf(-fabsf(s));
    float pm = 1.0f / (1.0f + e);
    float p  = (s >= 0.0f) ? pm : 1.0f - pm;
    float sp = fmaxf(s, 0.0f) + log1pf(e);
    ent  = sp - s * p;
    samp = (u01 < p) ? 1.0f : 0.0f;
}

// ---------------------------------------------------------------------------
// Kernel A: edge MLP — shuffle reduction, single barrier.
// ---------------------------------------------------------------------------
__global__ void edge_mlp_kernel(const float* __restrict__ eq,
                                const float* __restrict__ w1,
                                const float* __restrict__ b1,
                                const float* __restrict__ w2,
                                const float* __restrict__ b2,
                                float* __restrict__ out_w) {
    __shared__ float row[ND];
    __shared__ float part[4];
    int r = blockIdx.x;
    int t = threadIdx.x;  // 128
    if (t < ND) row[t] = eq[r * ND + t];
    __syncthreads();
    float acc = b1[t];
#pragma unroll
    for (int d = 0; d < ND; ++d)
        acc = fmaf(row[d], w1[d * NHM + t], acc);
    float val = fmaxf(acc, 0.0f) * w2[t];
#pragma unroll
    for (int off = 16; off > 0; off >>= 1)
        val += __shfl_down_sync(0xffffffffu, val, off);
    if ((t & 31) == 0) part[t >> 5] = val;
    __syncthreads();
    if (t == 0) {
        float wlog = (part[0] + part[1]) + (part[2] + part[3]) + b2[0];
        float e  = expf(-fabsf(wlog));
        float sp = fmaxf(wlog, 0.0f) + log1pf(e);
        out_w[r] = sp + 1e-8f;
    }
}

// ---------------------------------------------------------------------------
// Kernel B: P = exp(2*(enc@wl)), Q = exp(2*(enc@wr))  (unchanged; passed)
// ---------------------------------------------------------------------------
#define BM 32
__global__ void proj_kernel(const float* __restrict__ enc,
                            const float* __restrict__ wl,
                            const float* __restrict__ wr) {
    __shared__ float Ws[64][128];
    __shared__ float Es[BM][64];
    int t = threadIdx.x;            // 256
    int c = t & 127;
    int half = t >> 7;
    int row0 = blockIdx.x * BM;

    float acc[16];
#pragma unroll
    for (int i = 0; i < 16; ++i) acc[i] = 0.0f;

    for (int k0 = 0; k0 < NE; k0 += 64) {
        __syncthreads();
#pragma unroll
        for (int i = 0; i < 32; ++i) {
            int idx = t + i * 256;
            int kk = idx >> 7, cc = idx & 127;
            float v = (cc < 64) ? wl[(k0 + kk) * 64 + cc]
                                : wr[(k0 + kk) * 64 + (cc - 64)];
            Ws[kk][cc] = v;
        }
#pragma unroll
        for (int i = 0; i < 8; ++i) {
            int idx = t + i * 256;
            int rr = idx >> 6, kk = idx & 63;
            Es[rr][kk] = enc[(row0 + rr) * NE + k0 + kk];
        }
        __syncthreads();
#pragma unroll 8
        for (int k = 0; k < 64; ++k) {
            float wv = Ws[k][c];
#pragma unroll
            for (int rr = 0; rr < 16; ++rr)
                acc[rr] = fmaf(Es[half * 16 + rr][k], wv, acc[rr]);
        }
    }
#pragma unroll
    for (int rr = 0; rr < 16; ++rr) {
        int row = row0 + half * 16 + rr;
        float v = expf(2.0f * acc[rr]);
        if (c < 64) g_P[row * 64 + c]        = v;
        else        g_Q[row * 64 + (c - 64)] = v;
    }
}

// ---------------------------------------------------------------------------
// Kernel C: pair kernel, paired-reciprocal main loop.
// Per output, per h-pair (h0,h1):
//   d1 = p0*q0+1, d2 = p1*q1+1
//   acc += (v0*d2 + v1*d1) * rcp(d1*d2)      [6 FMA-pipe + 1 MUFU / 2 terms]
// Tile: 8 i x 64 j x 1 batch per block (z = batch), 128 threads,
// each thread: 2 i's x 2 j's = 4 outputs.
// ---------------------------------------------------------------------------
#define TIP 8
#define TJP 64
__global__ void __launch_bounds__(128) pair_kernel(
        const float* __restrict__ u,
        const float* __restrict__ l_bias,
        float* __restrict__ out) {
    __shared__ __align__(8) float ps[TIP * 64];     // [ii][h]
    __shared__ __align__(8) float qs[TJP * 66];     // [jj][h], pad 66 (even)
    __shared__ __align__(8) float vsm[64];          // v_h = -2 u_h

    int tid = threadIdx.x;                  // 128
    int bz  = blockIdx.z;
    int i0  = blockIdx.y * TIP;
    int j0  = blockIdx.x * TJP;

    if (tid < 64) vsm[tid] = -2.0f * u[tid];
#pragma unroll
    for (int it = 0; it < (TIP * 64) / 128; ++it) {      // 4
        int idx = tid + it * 128;
        ps[idx] = g_P[(bz * NN + i0) * 64 + idx];
    }
#pragma unroll
    for (int it = 0; it < (TJP * 64) / 128; ++it) {      // 32
        int idx = tid + it * 128;
        int jj = idx >> 6, h = idx & 63;
        qs[jj * 66 + h] = g_Q[(bz * NN + j0 + jj) * 64 + h];
    }
    __syncthreads();

    // sbase = sum_h u_h + l_bias = -0.5 * sum vsm + l_bias
    float Us = 0.0f;
    const float2* vp = (const float2*)vsm;
#pragma unroll
    for (int k = 0; k < 32; ++k) { float2 v2 = vp[k]; Us += v2.x + v2.y; }
    float sbase = -0.5f * Us + l_bias[0];

    int w = tid >> 5, l = tid & 31;
    const float2* pA = (const float2*)(ps + (w * 2) * 64);       // i = i0+2w
    const float2* pB = (const float2*)(ps + (w * 2 + 1) * 64);   // i = i0+2w+1
    const float2* qA = (const float2*)(qs + l * 66);             // j = j0+l
    const float2* qB = (const float2*)(qs + (l + 32) * 66);      // j = j0+l+32

    float a00 = 0.f, a01 = 0.f, a10 = 0.f, a11 = 0.f;

#pragma unroll 8
    for (int hp = 0; hp < 32; ++hp) {
        float2 vv = vp[hp];
        float2 pa = pA[hp], pb = pB[hp];
        float2 qa = qA[hp], qb = qB[hp];

        {   // (iA, jA)
            float d1 = fmaf(pa.x, qa.x, 1.0f);
            float d2 = fmaf(pa.y, qa.y, 1.0f);
            float nm = fmaf(vv.y, d1, vv.x * d2);
            a00 = fmaf(nm, frcp(d1 * d2), a00);
        }
        {   // (iA, jB)
            float d1 = fmaf(pa.x, qb.x, 1.0f);
            float d2 = fmaf(pa.y, qb.y, 1.0f);
            float nm = fmaf(vv.y, d1, vv.x * d2);
            a01 = fmaf(nm, frcp(d1 * d2), a01);
        }
        {   // (iB, jA)
            float d1 = fmaf(pb.x, qa.x, 1.0f);
            float d2 = fmaf(pb.y, qa.y, 1.0f);
            float nm = fmaf(vv.y, d1, vv.x * d2);
            a10 = fmaf(nm, frcp(d1 * d2), a10);
        }
        {   // (iB, jB)
            float d1 = fmaf(pb.x, qb.x, 1.0f);
            float d2 = fmaf(pb.y, qb.y, 1.0f);
            float nm = fmaf(vv.y, d1, vv.x * d2);
            a11 = fmaf(nm, frcp(d1 * d2), a11);
        }
    }

    float* out_s = out;
    float* out_m = out + OUT_TOTAL_PER;
    float* out_e = out + 2 * OUT_TOTAL_PER;

    float accs[2][2] = {{a00, a01}, {a10, a11}};
    uint32_t boff = bz * HALF;

#pragma unroll
    for (int r = 0; r < 2; ++r) {
        int gi = i0 + w * 2 + r;
#pragma unroll
        for (int q = 0; q < 2; ++q) {
            int gj = j0 + l + 32 * q;
            uint32_t m = (uint32_t)(gi * 1024 + gj);
            float u01 = bits_to_uniform(threefry_bits32(0u, boff + m));
            float diag = (gi == gj) ? 1e8f : 0.0f;
            float s = (sbase + accs[r][q]) - diag;
            float samp, ent;
            finish(s, u01, samp, ent);
            uint32_t o = boff + m;
            out_s[o] = samp; out_m[o] = s; out_e[o] = ent;
        }
    }
}

// ---------------------------------------------------------------------------
extern "C" void kernel_launch(void* const* d_in, const int* in_sizes, int n_in,
                              void* d_out, int out_size) {
    (void)in_sizes; (void)n_in; (void)out_size;
    const float* enc = (const float*)d_in[0];
    const float* wl  = (const float*)d_in[1];
    const float* wr  = (const float*)d_in[2];
    const float* u   = (const float*)d_in[3];
    const float* lb  = (const float*)d_in[4];
    const float* eq  = (const float*)d_in[5];
    const float* w1  = (const float*)d_in[6];
    const float* b1  = (const float*)d_in[7];
    const float* w2  = (const float*)d_in[8];
    const float* b2  = (const float*)d_in[9];
    float* out = (float*)d_out;

    edge_mlp_kernel<<<NN, NHM>>>(eq, w1, b1, w2, b2, out + 3 * OUT_TOTAL_PER);
    proj_kernel<<<(NB * NN) / BM, 256>>>(enc, wl, wr);
    dim3 grid(NN / TJP, NN / TIP, NB);   // (16, 128, 2)
    pair_kernel<<<grid, 128>>>(u, lb, out);
}